// round 1
// baseline (speedup 1.0000x reference)
#include <cuda_runtime.h>
#include <math.h>

#define DIMX 1024
#define NH   16
#define HD   64
#define DFF  4096
#define BB   2
#define SSQ  2048
#define MTOT (BB*SSQ)   /* 4096 rows */
#define EPSV 1e-6f

// ---------------- scratch (device globals: no allocation allowed) ----------
__device__ float g_h   [MTOT*DIMX];
__device__ float g_q   [MTOT*DIMX];
__device__ float g_k   [MTOT*DIMX];
__device__ float g_v   [MTOT*DIMX];
__device__ float g_attn[MTOT*DIMX];
__device__ float g_x2  [MTOT*DIMX];
__device__ float g_ffh [MTOT*DFF];

// ---------------- LayerNorm (torch-style: unbiased std, denom = std+eps) ---
__global__ void __launch_bounds__(256) ln_kernel(
    const float* __restrict__ x, const float* __restrict__ alpha,
    const float* __restrict__ beta, float* __restrict__ y)
{
    int row = blockIdx.x;
    int t = threadIdx.x;
    const float4* xr = reinterpret_cast<const float4*>(x + (size_t)row * DIMX);
    float4 v = xr[t];
    float s  = v.x + v.y + v.z + v.w;
    float sq = v.x*v.x + v.y*v.y + v.z*v.z + v.w*v.w;
    #pragma unroll
    for (int o = 16; o; o >>= 1) {
        s  += __shfl_xor_sync(0xffffffffu, s,  o);
        sq += __shfl_xor_sync(0xffffffffu, sq, o);
    }
    __shared__ float ss[8], ssq[8];
    int w = t >> 5, l = t & 31;
    if (l == 0) { ss[w] = s; ssq[w] = sq; }
    __syncthreads();
    if (w == 0) {
        s  = (l < 8) ? ss[l]  : 0.f;
        sq = (l < 8) ? ssq[l] : 0.f;
        #pragma unroll
        for (int o = 4; o; o >>= 1) {
            s  += __shfl_xor_sync(0xffffffffu, s,  o);
            sq += __shfl_xor_sync(0xffffffffu, sq, o);
        }
        if (l == 0) { ss[0] = s; ssq[0] = sq; }
    }
    __syncthreads();
    s = ss[0]; sq = ssq[0];
    float mu  = s * (1.0f / DIMX);
    float var = (sq - (float)DIMX * mu * mu) * (1.0f / (DIMX - 1));
    float sig = sqrtf(fmaxf(var, 0.f));
    float inv = 1.0f / (sig + EPSV);
    float4 a = reinterpret_cast<const float4*>(alpha)[t];
    float4 b = reinterpret_cast<const float4*>(beta)[t];
    float4 o4;
    o4.x = a.x * (v.x - mu) * inv + b.x;
    o4.y = a.y * (v.y - mu) * inv + b.y;
    o4.z = a.z * (v.z - mu) * inv + b.z;
    o4.w = a.w * (v.w - mu) * inv + b.w;
    reinterpret_cast<float4*>(y + (size_t)row * DIMX)[t] = o4;
}

// ---------------- fp32 SGEMM: C = A[M,K] @ B[K,N] (+bias)(+relu)(+res) -----
// 128x128x8 tiles, 256 threads, 8x8 microtile.
template<bool BIAS, bool RELU, bool RES>
__global__ void __launch_bounds__(256) sgemm_kernel(
    const float* __restrict__ A, const float* __restrict__ B,
    const float* __restrict__ bias, const float* __restrict__ res,
    float* __restrict__ C, int M, int N, int K)
{
    __shared__ float As[8][128];
    __shared__ float Bs[8][128];
    int tid = threadIdx.x;
    int bm = blockIdx.y * 128;
    int bn = blockIdx.x * 128;
    int ty = tid >> 4, tx = tid & 15;

    int arow = tid >> 1;
    int acol = (tid & 1) * 4;
    int brow = tid >> 5;
    int bcol = (tid & 31) * 4;

    const float* Aptr = A + (size_t)(bm + arow) * K + acol;
    const float* Bptr = B + (size_t)brow * N + bn + bcol;

    float acc[8][8];
    #pragma unroll
    for (int i = 0; i < 8; i++)
        #pragma unroll
        for (int j = 0; j < 8; j++) acc[i][j] = 0.f;

    for (int kt = 0; kt < K; kt += 8) {
        float4 av = *reinterpret_cast<const float4*>(Aptr + kt);
        float4 bv = *reinterpret_cast<const float4*>(Bptr + (size_t)kt * N);
        __syncthreads();
        As[acol + 0][arow] = av.x;
        As[acol + 1][arow] = av.y;
        As[acol + 2][arow] = av.z;
        As[acol + 3][arow] = av.w;
        *reinterpret_cast<float4*>(&Bs[brow][bcol]) = bv;
        __syncthreads();
        #pragma unroll
        for (int kk = 0; kk < 8; kk++) {
            float a[8], b[8];
            *reinterpret_cast<float4*>(&a[0]) = *reinterpret_cast<const float4*>(&As[kk][ty * 8]);
            *reinterpret_cast<float4*>(&a[4]) = *reinterpret_cast<const float4*>(&As[kk][ty * 8 + 4]);
            *reinterpret_cast<float4*>(&b[0]) = *reinterpret_cast<const float4*>(&Bs[kk][tx * 8]);
            *reinterpret_cast<float4*>(&b[4]) = *reinterpret_cast<const float4*>(&Bs[kk][tx * 8 + 4]);
            #pragma unroll
            for (int i = 0; i < 8; i++)
                #pragma unroll
                for (int j = 0; j < 8; j++)
                    acc[i][j] += a[i] * b[j];
        }
    }

    int crow = bm + ty * 8;
    int ccol = bn + tx * 8;
    #pragma unroll
    for (int i = 0; i < 8; i++) {
        size_t roff = (size_t)(crow + i) * N + ccol;
        #pragma unroll
        for (int j = 0; j < 8; j += 4) {
            float4 r;
            r.x = acc[i][j + 0]; r.y = acc[i][j + 1];
            r.z = acc[i][j + 2]; r.w = acc[i][j + 3];
            if (BIAS) {
                float4 bv = *reinterpret_cast<const float4*>(bias + ccol + j);
                r.x += bv.x; r.y += bv.y; r.z += bv.z; r.w += bv.w;
            }
            if (RELU) {
                r.x = fmaxf(r.x, 0.f); r.y = fmaxf(r.y, 0.f);
                r.z = fmaxf(r.z, 0.f); r.w = fmaxf(r.w, 0.f);
            }
            if (RES) {
                float4 rv = *reinterpret_cast<const float4*>(res + roff + j);
                r.x += rv.x; r.y += rv.y; r.z += rv.z; r.w += rv.w;
            }
            *reinterpret_cast<float4*>(C + roff + j) = r;
        }
    }
}

// ---------------- fused flash-style attention (fp32) ------------------------
// One block: 128 query rows of one (b,h). Streams 64-key tiles with online
// softmax. smem (dynamic): Qs[d][row] 64x128, Ks[d][col] 64x(64 pad 68),
// Vs[j][d] 64x68, Ps[j][row] 64x132.
#define ATQ 128
#define ATK 64
#define SQ_ 128
#define SK_ 68
#define SV_ 68
#define SP_ 132
#define ATT_SMEM ((64*SQ_ + 64*SK_ + 64*SV_ + 64*SP_) * 4)

__global__ void __launch_bounds__(256) attn_kernel(
    const float* __restrict__ q, const float* __restrict__ k,
    const float* __restrict__ v, float* __restrict__ o)
{
    extern __shared__ float sm[];
    float* Qs = sm;
    float* Ks = Qs + 64 * SQ_;
    float* Vs = Ks + 64 * SK_;
    float* Ps = Vs + 64 * SV_;

    int tid = threadIdx.x;
    int bh = blockIdx.y;
    int b = bh >> 4, h = bh & 15;
    int q0 = blockIdx.x * ATQ;
    size_t base = ((size_t)b * SSQ) * DIMX + h * HD;

    // load Q tile transposed: Qs[d][row]
    {
        int row = tid >> 1;
        int d0 = (tid & 1) * 32;
        const float* src = q + base + (size_t)(q0 + row) * DIMX + d0;
        #pragma unroll
        for (int i = 0; i < 8; i++) {
            float4 t4 = *reinterpret_cast<const float4*>(src + i * 4);
            Qs[(d0 + i * 4 + 0) * SQ_ + row] = t4.x;
            Qs[(d0 + i * 4 + 1) * SQ_ + row] = t4.y;
            Qs[(d0 + i * 4 + 2) * SQ_ + row] = t4.z;
            Qs[(d0 + i * 4 + 3) * SQ_ + row] = t4.w;
        }
    }

    int ty = tid >> 4, tx = tid & 15;   // rows ty*8..+7, S-cols tx*4..+3, O-cols tx*4..+3
    float m[8], l[8], oacc[8][4];
    #pragma unroll
    for (int i = 0; i < 8; i++) {
        m[i] = -1e30f; l[i] = 0.f;
        #pragma unroll
        for (int d = 0; d < 4; d++) oacc[i][d] = 0.f;
    }

    for (int kt = 0; kt < SSQ; kt += ATK) {
        __syncthreads();
        // load K tile transposed Ks[d][col], V tile Vs[j][d]
        {
            int col = tid >> 2;
            int d0 = (tid & 3) * 16;
            const float* srcK = k + base + (size_t)(kt + col) * DIMX + d0;
            const float* srcV = v + base + (size_t)(kt + col) * DIMX + d0;
            #pragma unroll
            for (int i = 0; i < 4; i++) {
                float4 t4 = *reinterpret_cast<const float4*>(srcK + i * 4);
                Ks[(d0 + i * 4 + 0) * SK_ + col] = t4.x;
                Ks[(d0 + i * 4 + 1) * SK_ + col] = t4.y;
                Ks[(d0 + i * 4 + 2) * SK_ + col] = t4.z;
                Ks[(d0 + i * 4 + 3) * SK_ + col] = t4.w;
                float4 v4 = *reinterpret_cast<const float4*>(srcV + i * 4);
                *reinterpret_cast<float4*>(&Vs[col * SV_ + d0 + i * 4]) = v4;
            }
        }
        __syncthreads();

        // S = (Q K^T) * 1/sqrt(HD)
        float s[8][4];
        #pragma unroll
        for (int i = 0; i < 8; i++)
            #pragma unroll
            for (int j = 0; j < 4; j++) s[i][j] = 0.f;
        #pragma unroll 4
        for (int kk = 0; kk < 64; kk++) {
            float a[8], bb4[4];
            *reinterpret_cast<float4*>(&a[0]) = *reinterpret_cast<const float4*>(&Qs[kk * SQ_ + ty * 8]);
            *reinterpret_cast<float4*>(&a[4]) = *reinterpret_cast<const float4*>(&Qs[kk * SQ_ + ty * 8 + 4]);
            *reinterpret_cast<float4*>(&bb4[0]) = *reinterpret_cast<const float4*>(&Ks[kk * SK_ + tx * 4]);
            #pragma unroll
            for (int i = 0; i < 8; i++)
                #pragma unroll
                for (int j = 0; j < 4; j++)
                    s[i][j] += a[i] * bb4[j];
        }

        // online softmax
        #pragma unroll
        for (int i = 0; i < 8; i++) {
            #pragma unroll
            for (int j = 0; j < 4; j++) s[i][j] *= 0.125f;
            float mi = s[i][0];
            mi = fmaxf(mi, s[i][1]); mi = fmaxf(mi, s[i][2]); mi = fmaxf(mi, s[i][3]);
            mi = fmaxf(mi, __shfl_xor_sync(0xffffffffu, mi, 1));
            mi = fmaxf(mi, __shfl_xor_sync(0xffffffffu, mi, 2));
            mi = fmaxf(mi, __shfl_xor_sync(0xffffffffu, mi, 4));
            mi = fmaxf(mi, __shfl_xor_sync(0xffffffffu, mi, 8));
            float mn = fmaxf(m[i], mi);
            float corr = __expf(m[i] - mn);
            m[i] = mn;
            float ls = 0.f;
            #pragma unroll
            for (int j = 0; j < 4; j++) {
                float p = __expf(s[i][j] - mn);
                s[i][j] = p; ls += p;
            }
            ls += __shfl_xor_sync(0xffffffffu, ls, 1);
            ls += __shfl_xor_sync(0xffffffffu, ls, 2);
            ls += __shfl_xor_sync(0xffffffffu, ls, 4);
            ls += __shfl_xor_sync(0xffffffffu, ls, 8);
            l[i] = l[i] * corr + ls;
            #pragma unroll
            for (int d = 0; d < 4; d++) oacc[i][d] *= corr;
        }

        // share P via smem: Ps[j][row]
        #pragma unroll
        for (int i = 0; i < 8; i++)
            #pragma unroll
            for (int j = 0; j < 4; j++)
                Ps[(tx * 4 + j) * SP_ + ty * 8 + i] = s[i][j];
        __syncthreads();

        // O += P @ V
        #pragma unroll 4
        for (int j = 0; j < 64; j++) {
            float p[8], vv[4];
            *reinterpret_cast<float4*>(&p[0]) = *reinterpret_cast<const float4*>(&Ps[j * SP_ + ty * 8]);
            *reinterpret_cast<float4*>(&p[4]) = *reinterpret_cast<const float4*>(&Ps[j * SP_ + ty * 8 + 4]);
            *reinterpret_cast<float4*>(&vv[0]) = *reinterpret_cast<const float4*>(&Vs[j * SV_ + tx * 4]);
            #pragma unroll
            for (int i = 0; i < 8; i++)
                #pragma unroll
                for (int d = 0; d < 4; d++)
                    oacc[i][d] += p[i] * vv[d];
        }
    }

    // epilogue: divide by l, store
    #pragma unroll
    for (int i = 0; i < 8; i++) {
        float invl = 1.0f / l[i];
        float4 r;
        r.x = oacc[i][0] * invl; r.y = oacc[i][1] * invl;
        r.z = oacc[i][2] * invl; r.w = oacc[i][3] * invl;
        int row = q0 + ty * 8 + i;
        *reinterpret_cast<float4*>(o + base + (size_t)row * DIMX + tx * 4) = r;
    }
}

// ---------------- launch -----------------------------------------------------
extern "C" void kernel_launch(void* const* d_in, const int* in_sizes, int n_in,
                              void* d_out, int out_size)
{
    const float* x    = (const float*)d_in[0];
    // d_in[1] = mask (no-op in reference)
    const float* wq   = (const float*)d_in[2];
    const float* wk   = (const float*)d_in[3];
    const float* wv   = (const float*)d_in[4];
    const float* wo   = (const float*)d_in[5];
    const float* w_up = (const float*)d_in[6];
    const float* b_up = (const float*)d_in[7];
    const float* w_dn = (const float*)d_in[8];
    const float* b_dn = (const float*)d_in[9];
    const float* l1a  = (const float*)d_in[10];
    const float* l1b  = (const float*)d_in[11];
    const float* l2a  = (const float*)d_in[12];
    const float* l2b  = (const float*)d_in[13];
    float* out = (float*)d_out;

    float *h, *qb, *kb, *vb, *attn, *x2, *ffh;
    cudaGetSymbolAddress((void**)&h,    g_h);
    cudaGetSymbolAddress((void**)&qb,   g_q);
    cudaGetSymbolAddress((void**)&kb,   g_k);
    cudaGetSymbolAddress((void**)&vb,   g_v);
    cudaGetSymbolAddress((void**)&attn, g_attn);
    cudaGetSymbolAddress((void**)&x2,   g_x2);
    cudaGetSymbolAddress((void**)&ffh,  g_ffh);

    cudaFuncSetAttribute(attn_kernel, cudaFuncAttributeMaxDynamicSharedMemorySize, ATT_SMEM);

    dim3 thr(256);

    // h = LN1(x)
    ln_kernel<<<MTOT, thr>>>(x, l1a, l1b, h);

    // q, k, v projections
    sgemm_kernel<false, false, false><<<dim3(DIMX / 128, MTOT / 128), thr>>>(h, wq, nullptr, nullptr, qb, MTOT, DIMX, DIMX);
    sgemm_kernel<false, false, false><<<dim3(DIMX / 128, MTOT / 128), thr>>>(h, wk, nullptr, nullptr, kb, MTOT, DIMX, DIMX);
    sgemm_kernel<false, false, false><<<dim3(DIMX / 128, MTOT / 128), thr>>>(h, wv, nullptr, nullptr, vb, MTOT, DIMX, DIMX);

    // attention
    attn_kernel<<<dim3(SSQ / ATQ, BB * NH), thr, ATT_SMEM>>>(qb, kb, vb, attn);

    // x2 = x + attn @ wo
    sgemm_kernel<false, false, true><<<dim3(DIMX / 128, MTOT / 128), thr>>>(attn, wo, nullptr, x, x2, MTOT, DIMX, DIMX);

    // h = LN2(x2)
    ln_kernel<<<MTOT, thr>>>(x2, l2a, l2b, h);

    // ffh = relu(h @ w_up + b_up)
    sgemm_kernel<true, true, false><<<dim3(DFF / 128, MTOT / 128), thr>>>(h, w_up, b_up, nullptr, ffh, MTOT, DFF, DIMX);

    // out = x2 + ffh @ w_down + b_down
    sgemm_kernel<true, false, true><<<dim3(DIMX / 128, MTOT / 128), thr>>>(ffh, w_dn, b_dn, x2, out, MTOT, DIMX, DFF);
}

// round 2
// speedup vs baseline: 2.7957x; 2.7957x over previous
#include <cuda_runtime.h>
#include <math.h>

#define DIMX 1024
#define NH   16
#define HD   64
#define DFF  4096
#define BB   2
#define SSQ  2048
#define MTOT (BB*SSQ)
#define EPSV 1e-6f

// ---------------- scratch (device globals) ----------------------------------
__device__ float g_h   [MTOT*DIMX];
__device__ float g_q   [MTOT*DIMX];
__device__ float g_k   [MTOT*DIMX];
__device__ float g_v   [MTOT*DIMX];
__device__ float g_attn[MTOT*DIMX];
__device__ float g_x2  [MTOT*DIMX];
__device__ float g_ffh [MTOT*DFF];

// ---------------- helpers ----------------------------------------------------
__device__ __forceinline__ unsigned f2tf(float f) {
    unsigned u;
    asm("cvt.rna.tf32.f32 %0, %1;" : "=r"(u) : "f"(f));
    return u;
}

#define MMA_TF32(c, a, b) asm volatile( \
    "mma.sync.aligned.m16n8k8.row.col.f32.tf32.tf32.f32 " \
    "{%0,%1,%2,%3}, {%4,%5,%6,%7}, {%8,%9}, {%0,%1,%2,%3};" \
    : "+f"((c)[0]), "+f"((c)[1]), "+f"((c)[2]), "+f"((c)[3]) \
    : "r"((a)[0]), "r"((a)[1]), "r"((a)[2]), "r"((a)[3]), \
      "r"((b)[0]), "r"((b)[1]))

// ---------------- LayerNorm --------------------------------------------------
__global__ void __launch_bounds__(256) ln_kernel(
    const float* __restrict__ x, const float* __restrict__ alpha,
    const float* __restrict__ beta, float* __restrict__ y)
{
    int row = blockIdx.x;
    int t = threadIdx.x;
    const float4* xr = reinterpret_cast<const float4*>(x + (size_t)row * DIMX);
    float4 v = xr[t];
    float s  = v.x + v.y + v.z + v.w;
    float sq = v.x*v.x + v.y*v.y + v.z*v.z + v.w*v.w;
    #pragma unroll
    for (int o = 16; o; o >>= 1) {
        s  += __shfl_xor_sync(0xffffffffu, s,  o);
        sq += __shfl_xor_sync(0xffffffffu, sq, o);
    }
    __shared__ float ss[8], ssq[8];
    int w = t >> 5, l = t & 31;
    if (l == 0) { ss[w] = s; ssq[w] = sq; }
    __syncthreads();
    if (w == 0) {
        s  = (l < 8) ? ss[l]  : 0.f;
        sq = (l < 8) ? ssq[l] : 0.f;
        #pragma unroll
        for (int o = 4; o; o >>= 1) {
            s  += __shfl_xor_sync(0xffffffffu, s,  o);
            sq += __shfl_xor_sync(0xffffffffu, sq, o);
        }
        if (l == 0) { ss[0] = s; ssq[0] = sq; }
    }
    __syncthreads();
    s = ss[0]; sq = ssq[0];
    float mu  = s * (1.0f / DIMX);
    float var = (sq - (float)DIMX * mu * mu) * (1.0f / (DIMX - 1));
    float sig = sqrtf(fmaxf(var, 0.f));
    float inv = 1.0f / (sig + EPSV);
    float4 a = reinterpret_cast<const float4*>(alpha)[t];
    float4 b = reinterpret_cast<const float4*>(beta)[t];
    float4 o4;
    o4.x = a.x * (v.x - mu) * inv + b.x;
    o4.y = a.y * (v.y - mu) * inv + b.y;
    o4.z = a.z * (v.z - mu) * inv + b.z;
    o4.w = a.w * (v.w - mu) * inv + b.w;
    reinterpret_cast<float4*>(y + (size_t)row * DIMX)[t] = o4;
}

// ---------------- TF32 tensor-core GEMM --------------------------------------
// C[M,N] = A[M,K] @ B[K,N] (+bias)(+relu)(+res). 128x128x32 tiles, 256 thr.
// Warp tile 64x32 (4 m-frags x 4 n-frags of m16n8k8).
#define GPA 36
#define GPB 136
#define GEMM_SMEM ((2*128*GPA + 2*32*GPB) * 4)

template<bool BIAS, bool RELU, bool RES>
__global__ void __launch_bounds__(256) gemm_tf32(
    const float* __restrict__ A, const float* __restrict__ B,
    const float* __restrict__ bias, const float* __restrict__ res,
    float* __restrict__ C, int M, int N, int K)
{
    extern __shared__ unsigned smg[];
    unsigned* As = smg;                    // [2][128][GPA]
    unsigned* Bs = smg + 2 * 128 * GPA;    // [2][32][GPB]

    const int tid  = threadIdx.x;
    const int bm   = blockIdx.y * 128, bn = blockIdx.x * 128;
    const int warp = tid >> 5, lane = tid & 31;
    const int wm   = (warp >> 2) << 6;
    const int wn   = (warp & 3) << 5;
    const int g    = lane >> 2, q = lane & 3;

    const int arow = tid >> 3;
    const int acol = (tid & 7) << 2;
    const int brow = tid >> 5;
    const int bcol = (tid & 31) << 2;

    const float* Ag = A + (size_t)(bm + arow) * K + acol;
    const float* Bg = B + (size_t)brow * N + bn + bcol;

    float acc[4][4][4];
    #pragma unroll
    for (int mi = 0; mi < 4; mi++)
        #pragma unroll
        for (int nj = 0; nj < 4; nj++)
            #pragma unroll
            for (int e = 0; e < 4; e++) acc[mi][nj][e] = 0.f;

    float4 ra[4], rb[4];
    #pragma unroll
    for (int i = 0; i < 4; i++) {
        ra[i] = *reinterpret_cast<const float4*>(Ag + (size_t)(i * 32) * K);
        rb[i] = *reinterpret_cast<const float4*>(Bg + (size_t)(i * 8) * N);
    }

    #define G_STORE_TILE(bufi) do { \
        unsigned* Ab_ = As + (bufi) * 128 * GPA; \
        unsigned* Bb_ = Bs + (bufi) * 32 * GPB; \
        _Pragma("unroll") \
        for (int i_ = 0; i_ < 4; i_++) { \
            uint4 ua; ua.x = f2tf(ra[i_].x); ua.y = f2tf(ra[i_].y); \
                      ua.z = f2tf(ra[i_].z); ua.w = f2tf(ra[i_].w); \
            *reinterpret_cast<uint4*>(Ab_ + (arow + 32 * i_) * GPA + acol) = ua; \
            uint4 ub; ub.x = f2tf(rb[i_].x); ub.y = f2tf(rb[i_].y); \
                      ub.z = f2tf(rb[i_].z); ub.w = f2tf(rb[i_].w); \
            *reinterpret_cast<uint4*>(Bb_ + (brow + 8 * i_) * GPB + bcol) = ub; \
        } \
    } while (0)

    G_STORE_TILE(0);
    __syncthreads();

    const int nt = K >> 5;
    for (int kt = 0; kt < nt; kt++) {
        const int cur = kt & 1;
        if (kt + 1 < nt) {
            const float* Ap = Ag + (kt + 1) * 32;
            const float* Bp = Bg + (size_t)(kt + 1) * 32 * N;
            #pragma unroll
            for (int i = 0; i < 4; i++) {
                ra[i] = *reinterpret_cast<const float4*>(Ap + (size_t)(i * 32) * K);
                rb[i] = *reinterpret_cast<const float4*>(Bp + (size_t)(i * 8) * N);
            }
        }
        const unsigned* Ab = As + cur * 128 * GPA;
        const unsigned* Bb = Bs + cur * 32 * GPB;
        #pragma unroll
        for (int ks = 0; ks < 4; ks++) {
            const int kk = ks << 3;
            unsigned af[4][4], bf[4][2];
            #pragma unroll
            for (int mi = 0; mi < 4; mi++) {
                int r = wm + (mi << 4) + g;
                af[mi][0] = Ab[r * GPA + kk + q];
                af[mi][1] = Ab[(r + 8) * GPA + kk + q];
                af[mi][2] = Ab[r * GPA + kk + q + 4];
                af[mi][3] = Ab[(r + 8) * GPA + kk + q + 4];
            }
            #pragma unroll
            for (int nj = 0; nj < 4; nj++) {
                int c = wn + (nj << 3) + g;
                bf[nj][0] = Bb[(kk + q) * GPB + c];
                bf[nj][1] = Bb[(kk + q + 4) * GPB + c];
            }
            #pragma unroll
            for (int mi = 0; mi < 4; mi++)
                #pragma unroll
                for (int nj = 0; nj < 4; nj++)
                    MMA_TF32(acc[mi][nj], af[mi], bf[nj]);
        }
        if (kt + 1 < nt) {
            G_STORE_TILE((kt + 1) & 1);
            __syncthreads();
        }
    }

    // epilogue
    #pragma unroll
    for (int mi = 0; mi < 4; mi++) {
        int r = bm + wm + (mi << 4) + g;
        #pragma unroll
        for (int nj = 0; nj < 4; nj++) {
            int c = bn + wn + (nj << 3) + (q << 1);
            float2 v0, v1;
            v0.x = acc[mi][nj][0]; v0.y = acc[mi][nj][1];
            v1.x = acc[mi][nj][2]; v1.y = acc[mi][nj][3];
            if (BIAS) {
                float2 bv = *reinterpret_cast<const float2*>(bias + c);
                v0.x += bv.x; v0.y += bv.y; v1.x += bv.x; v1.y += bv.y;
            }
            if (RELU) {
                v0.x = fmaxf(v0.x, 0.f); v0.y = fmaxf(v0.y, 0.f);
                v1.x = fmaxf(v1.x, 0.f); v1.y = fmaxf(v1.y, 0.f);
            }
            if (RES) {
                float2 r0 = *reinterpret_cast<const float2*>(res + (size_t)r * N + c);
                float2 r1 = *reinterpret_cast<const float2*>(res + (size_t)(r + 8) * N + c);
                v0.x += r0.x; v0.y += r0.y; v1.x += r1.x; v1.y += r1.y;
            }
            *reinterpret_cast<float2*>(C + (size_t)r * N + c) = v0;
            *reinterpret_cast<float2*>(C + (size_t)(r + 8) * N + c) = v1;
        }
    }
}

// ---------------- TF32 flash attention ---------------------------------------
// Block: 128 q rows of one (b,h); 8 warps x 16 rows. Key tiles of 64.
// Qs[128][68], Ks[64][68] (as [key][d]), Vs[64][72] ([key][d]), Ps[128][68].
#define AQS 68
#define AKS 68
#define AVS 72
#define APS 68
#define ATT_SMEM ((128*AQS + 64*AKS + 64*AVS + 128*APS) * 4)

__global__ void __launch_bounds__(256) attn_tf32(
    const float* __restrict__ qg, const float* __restrict__ kg,
    const float* __restrict__ vg, float* __restrict__ og)
{
    extern __shared__ unsigned sma[];
    unsigned* Qs = sma;
    unsigned* Ks = Qs + 128 * AQS;
    unsigned* Vs = Ks + 64 * AKS;
    unsigned* Ps = Vs + 64 * AVS;

    const int tid  = threadIdx.x;
    const int warp = tid >> 5, lane = tid & 31;
    const int g    = lane >> 2, q4 = lane & 3;
    const int bh   = blockIdx.y;
    const int b    = bh >> 4, h = bh & 15;
    const int q0   = blockIdx.x * 128;
    const size_t base = ((size_t)b * SSQ) * DIMX + h * HD;
    const int r0 = warp << 4;

    // load Q tile: 2048 float4 / 256 thr = 8 each
    #pragma unroll
    for (int i = 0; i < 8; i++) {
        int f = tid + (i << 8);
        int row = f >> 4;
        int d4 = (f & 15) << 2;
        float4 t4 = *reinterpret_cast<const float4*>(qg + base + (size_t)(q0 + row) * DIMX + d4);
        uint4 u; u.x = f2tf(t4.x); u.y = f2tf(t4.y); u.z = f2tf(t4.z); u.w = f2tf(t4.w);
        *reinterpret_cast<uint4*>(Qs + row * AQS + d4) = u;
    }
    __syncthreads();

    // preload Q fragments (reused across all key tiles)
    unsigned aq[8][4];
    #pragma unroll
    for (int ks = 0; ks < 8; ks++) {
        int kk = ks << 3;
        aq[ks][0] = Qs[(r0 + g) * AQS + kk + q4];
        aq[ks][1] = Qs[(r0 + 8 + g) * AQS + kk + q4];
        aq[ks][2] = Qs[(r0 + g) * AQS + kk + q4 + 4];
        aq[ks][3] = Qs[(r0 + 8 + g) * AQS + kk + q4 + 4];
    }

    float m0 = -1e30f, m1 = -1e30f, l0 = 0.f, l1 = 0.f;
    float oacc[8][4];
    #pragma unroll
    for (int j = 0; j < 8; j++)
        #pragma unroll
        for (int e = 0; e < 4; e++) oacc[j][e] = 0.f;

    for (int kt = 0; kt < SSQ; kt += 64) {
        __syncthreads();
        // load K,V tiles: 1024 float4 each / 256 thr = 4 each
        #pragma unroll
        for (int i = 0; i < 4; i++) {
            int f = tid + (i << 8);
            int key = f >> 4;
            int d4 = (f & 15) << 2;
            size_t go = base + (size_t)(kt + key) * DIMX + d4;
            float4 tk = *reinterpret_cast<const float4*>(kg + go);
            float4 tv = *reinterpret_cast<const float4*>(vg + go);
            uint4 uk; uk.x = f2tf(tk.x); uk.y = f2tf(tk.y); uk.z = f2tf(tk.z); uk.w = f2tf(tk.w);
            uint4 uv; uv.x = f2tf(tv.x); uv.y = f2tf(tv.y); uv.z = f2tf(tv.z); uv.w = f2tf(tv.w);
            *reinterpret_cast<uint4*>(Ks + key * AKS + d4) = uk;
            *reinterpret_cast<uint4*>(Vs + key * AVS + d4) = uv;
        }
        __syncthreads();

        // S = Q K^T
        float s[8][4];
        #pragma unroll
        for (int j = 0; j < 8; j++)
            #pragma unroll
            for (int e = 0; e < 4; e++) s[j][e] = 0.f;
        #pragma unroll
        for (int ks = 0; ks < 8; ks++) {
            int kk = ks << 3;
            #pragma unroll
            for (int j = 0; j < 8; j++) {
                unsigned bfr[2];
                bfr[0] = Ks[((j << 3) + g) * AKS + kk + q4];
                bfr[1] = Ks[((j << 3) + g) * AKS + kk + q4 + 4];
                MMA_TF32(s[j], aq[ks], bfr);
            }
        }

        // online softmax (rows live in quads)
        float mt0 = -1e30f, mt1 = -1e30f;
        #pragma unroll
        for (int j = 0; j < 8; j++) {
            s[j][0] *= 0.125f; s[j][1] *= 0.125f; s[j][2] *= 0.125f; s[j][3] *= 0.125f;
            mt0 = fmaxf(mt0, fmaxf(s[j][0], s[j][1]));
            mt1 = fmaxf(mt1, fmaxf(s[j][2], s[j][3]));
        }
        mt0 = fmaxf(mt0, __shfl_xor_sync(0xffffffffu, mt0, 1));
        mt0 = fmaxf(mt0, __shfl_xor_sync(0xffffffffu, mt0, 2));
        mt1 = fmaxf(mt1, __shfl_xor_sync(0xffffffffu, mt1, 1));
        mt1 = fmaxf(mt1, __shfl_xor_sync(0xffffffffu, mt1, 2));
        float mn0 = fmaxf(m0, mt0), mn1 = fmaxf(m1, mt1);
        float corr0 = __expf(m0 - mn0), corr1 = __expf(m1 - mn1);
        m0 = mn0; m1 = mn1;
        float ls0 = 0.f, ls1 = 0.f;
        #pragma unroll
        for (int j = 0; j < 8; j++) {
            float p0 = __expf(s[j][0] - mn0);
            float p1 = __expf(s[j][1] - mn0);
            float p2 = __expf(s[j][2] - mn1);
            float p3 = __expf(s[j][3] - mn1);
            ls0 += p0 + p1; ls1 += p2 + p3;
            uint2 u0; u0.x = f2tf(p0); u0.y = f2tf(p1);
            uint2 u1; u1.x = f2tf(p2); u1.y = f2tf(p3);
            *reinterpret_cast<uint2*>(Ps + (r0 + g) * APS + (j << 3) + (q4 << 1)) = u0;
            *reinterpret_cast<uint2*>(Ps + (r0 + 8 + g) * APS + (j << 3) + (q4 << 1)) = u1;
        }
        ls0 += __shfl_xor_sync(0xffffffffu, ls0, 1);
        ls0 += __shfl_xor_sync(0xffffffffu, ls0, 2);
        ls1 += __shfl_xor_sync(0xffffffffu, ls1, 1);
        ls1 += __shfl_xor_sync(0xffffffffu, ls1, 2);
        l0 = l0 * corr0 + ls0;
        l1 = l1 * corr1 + ls1;
        #pragma unroll
        for (int j = 0; j < 8; j++) {
            oacc[j][0] *= corr0; oacc[j][1] *= corr0;
            oacc[j][2] *= corr1; oacc[j][3] *= corr1;
        }
        __syncwarp();

        // O += P @ V
        #pragma unroll
        for (int ks = 0; ks < 8; ks++) {
            int kk = ks << 3;
            unsigned ap[4];
            ap[0] = Ps[(r0 + g) * APS + kk + q4];
            ap[1] = Ps[(r0 + 8 + g) * APS + kk + q4];
            ap[2] = Ps[(r0 + g) * APS + kk + q4 + 4];
            ap[3] = Ps[(r0 + 8 + g) * APS + kk + q4 + 4];
            #pragma unroll
            for (int j = 0; j < 8; j++) {
                unsigned bfr[2];
                bfr[0] = Vs[(kk + q4) * AVS + (j << 3) + g];
                bfr[1] = Vs[(kk + q4 + 4) * AVS + (j << 3) + g];
                MMA_TF32(oacc[j], ap, bfr);
            }
        }
    }

    // epilogue
    float il0 = 1.0f / l0, il1 = 1.0f / l1;
    #pragma unroll
    for (int j = 0; j < 8; j++) {
        float2 v0, v1;
        v0.x = oacc[j][0] * il0; v0.y = oacc[j][1] * il0;
        v1.x = oacc[j][2] * il1; v1.y = oacc[j][3] * il1;
        size_t o0 = base + (size_t)(q0 + r0 + g) * DIMX + (j << 3) + (q4 << 1);
        size_t o1 = base + (size_t)(q0 + r0 + 8 + g) * DIMX + (j << 3) + (q4 << 1);
        *reinterpret_cast<float2*>(og + o0) = v0;
        *reinterpret_cast<float2*>(og + o1) = v1;
    }
}

// ---------------- launch ------------------------------------------------------
extern "C" void kernel_launch(void* const* d_in, const int* in_sizes, int n_in,
                              void* d_out, int out_size)
{
    const float* x    = (const float*)d_in[0];
    const float* wq   = (const float*)d_in[2];
    const float* wk   = (const float*)d_in[3];
    const float* wv   = (const float*)d_in[4];
    const float* wo   = (const float*)d_in[5];
    const float* w_up = (const float*)d_in[6];
    const float* b_up = (const float*)d_in[7];
    const float* w_dn = (const float*)d_in[8];
    const float* b_dn = (const float*)d_in[9];
    const float* l1a  = (const float*)d_in[10];
    const float* l1b  = (const float*)d_in[11];
    const float* l2a  = (const float*)d_in[12];
    const float* l2b  = (const float*)d_in[13];
    float* out = (float*)d_out;

    float *h, *qb, *kb, *vb, *attn, *x2, *ffh;
    cudaGetSymbolAddress((void**)&h,    g_h);
    cudaGetSymbolAddress((void**)&qb,   g_q);
    cudaGetSymbolAddress((void**)&kb,   g_k);
    cudaGetSymbolAddress((void**)&vb,   g_v);
    cudaGetSymbolAddress((void**)&attn, g_attn);
    cudaGetSymbolAddress((void**)&x2,   g_x2);
    cudaGetSymbolAddress((void**)&ffh,  g_ffh);

    cudaFuncSetAttribute(gemm_tf32<false,false,false>, cudaFuncAttributeMaxDynamicSharedMemorySize, GEMM_SMEM);
    cudaFuncSetAttribute(gemm_tf32<false,false,true >, cudaFuncAttributeMaxDynamicSharedMemorySize, GEMM_SMEM);
    cudaFuncSetAttribute(gemm_tf32<true ,true ,false>, cudaFuncAttributeMaxDynamicSharedMemorySize, GEMM_SMEM);
    cudaFuncSetAttribute(gemm_tf32<true ,false,true >, cudaFuncAttributeMaxDynamicSharedMemorySize, GEMM_SMEM);
    cudaFuncSetAttribute(attn_tf32, cudaFuncAttributeMaxDynamicSharedMemorySize, ATT_SMEM);

    dim3 thr(256);

    ln_kernel<<<MTOT, thr>>>(x, l1a, l1b, h);

    gemm_tf32<false,false,false><<<dim3(DIMX/128, MTOT/128), thr, GEMM_SMEM>>>(h, wq, nullptr, nullptr, qb, MTOT, DIMX, DIMX);
    gemm_tf32<false,false,false><<<dim3(DIMX/128, MTOT/128), thr, GEMM_SMEM>>>(h, wk, nullptr, nullptr, kb, MTOT, DIMX, DIMX);
    gemm_tf32<false,false,false><<<dim3(DIMX/128, MTOT/128), thr, GEMM_SMEM>>>(h, wv, nullptr, nullptr, vb, MTOT, DIMX, DIMX);

    attn_tf32<<<dim3(SSQ/128, BB*NH), thr, ATT_SMEM>>>(qb, kb, vb, attn);

    gemm_tf32<false,false,true><<<dim3(DIMX/128, MTOT/128), thr, GEMM_SMEM>>>(attn, wo, nullptr, x, x2, MTOT, DIMX, DIMX);

    ln_kernel<<<MTOT, thr>>>(x2, l2a, l2b, h);

    gemm_tf32<true,true,false><<<dim3(DFF/128, MTOT/128), thr, GEMM_SMEM>>>(h, w_up, b_up, nullptr, ffh, MTOT, DFF, DIMX);

    gemm_tf32<true,false,true><<<dim3(DIMX/128, MTOT/128), thr, GEMM_SMEM>>>(ffh, w_dn, b_dn, x2, out, MTOT, DIMX, DFF);
}

// round 3
// speedup vs baseline: 3.4869x; 1.2473x over previous
#include <cuda_runtime.h>
#include <math.h>

#define DIMX 1024
#define NH   16
#define HD   64
#define DFF  4096
#define BB   2
#define SSQ  2048
#define MTOT (BB*SSQ)
#define EPSV 1e-6f

// ---------------- scratch (device globals) ----------------------------------
__device__ float g_h   [MTOT*DIMX];
__device__ float g_q   [MTOT*DIMX];
__device__ float g_k   [MTOT*DIMX];
__device__ float g_v   [MTOT*DIMX];
__device__ float g_attn[MTOT*DIMX];
__device__ float g_x2  [MTOT*DIMX];
__device__ float g_ffh [MTOT*DFF];
__device__ float g_wc  [4*DIMX*DIMX + 2*DIMX*DFF];   // tf32-rounded weights

// ---------------- helpers ----------------------------------------------------
__device__ __forceinline__ unsigned f2tf(float f) {
    unsigned u;
    asm("cvt.rna.tf32.f32 %0, %1;" : "=r"(u) : "f"(f));
    return u;
}

__device__ __forceinline__ void cp16(unsigned s, const void* g) {
    asm volatile("cp.async.cg.shared.global [%0], [%1], 16;" :: "r"(s), "l"(g));
}
#define CP_COMMIT() asm volatile("cp.async.commit_group;")
#define CP_WAIT(n)  asm volatile("cp.async.wait_group %0;" :: "n"(n))

#define MMA_TF32(c, a, b) asm volatile( \
    "mma.sync.aligned.m16n8k8.row.col.f32.tf32.tf32.f32 " \
    "{%0,%1,%2,%3}, {%4,%5,%6,%7}, {%8,%9}, {%0,%1,%2,%3};" \
    : "+f"((c)[0]), "+f"((c)[1]), "+f"((c)[2]), "+f"((c)[3]) \
    : "r"((a)[0]), "r"((a)[1]), "r"((a)[2]), "r"((a)[3]), \
      "r"((b)[0]), "r"((b)[1]))

// ---------------- weight tf32 pre-round ---------------------------------------
__global__ void __launch_bounds__(256) cvt_kernel(const float* __restrict__ src,
                                                  float* __restrict__ dst, int n4)
{
    int i = blockIdx.x * 256 + threadIdx.x;
    if (i < n4) {
        float4 v = reinterpret_cast<const float4*>(src)[i];
        uint4 u;
        u.x = f2tf(v.x); u.y = f2tf(v.y); u.z = f2tf(v.z); u.w = f2tf(v.w);
        reinterpret_cast<uint4*>(dst)[i] = u;
    }
}

// ---------------- LayerNorm (emits tf32-rounded output) -----------------------
__global__ void __launch_bounds__(256) ln_kernel(
    const float* __restrict__ x, const float* __restrict__ alpha,
    const float* __restrict__ beta, float* __restrict__ y)
{
    int row = blockIdx.x;
    int t = threadIdx.x;
    const float4* xr = reinterpret_cast<const float4*>(x + (size_t)row * DIMX);
    float4 v = xr[t];
    float s  = v.x + v.y + v.z + v.w;
    float sq = v.x*v.x + v.y*v.y + v.z*v.z + v.w*v.w;
    #pragma unroll
    for (int o = 16; o; o >>= 1) {
        s  += __shfl_xor_sync(0xffffffffu, s,  o);
        sq += __shfl_xor_sync(0xffffffffu, sq, o);
    }
    __shared__ float ss[8], ssq[8];
    int w = t >> 5, l = t & 31;
    if (l == 0) { ss[w] = s; ssq[w] = sq; }
    __syncthreads();
    if (w == 0) {
        s  = (l < 8) ? ss[l]  : 0.f;
        sq = (l < 8) ? ssq[l] : 0.f;
        #pragma unroll
        for (int o = 4; o; o >>= 1) {
            s  += __shfl_xor_sync(0xffffffffu, s,  o);
            sq += __shfl_xor_sync(0xffffffffu, sq, o);
        }
        if (l == 0) { ss[0] = s; ssq[0] = sq; }
    }
    __syncthreads();
    s = ss[0]; sq = ssq[0];
    float mu  = s * (1.0f / DIMX);
    float var = (sq - (float)DIMX * mu * mu) * (1.0f / (DIMX - 1));
    float sig = sqrtf(fmaxf(var, 0.f));
    float inv = 1.0f / (sig + EPSV);
    float4 a = reinterpret_cast<const float4*>(alpha)[t];
    float4 b = reinterpret_cast<const float4*>(beta)[t];
    uint4 o4;
    o4.x = f2tf(a.x * (v.x - mu) * inv + b.x);
    o4.y = f2tf(a.y * (v.y - mu) * inv + b.y);
    o4.z = f2tf(a.z * (v.z - mu) * inv + b.z);
    o4.w = f2tf(a.w * (v.w - mu) * inv + b.w);
    reinterpret_cast<uint4*>(y + (size_t)row * DIMX)[t] = o4;
}

// ---------------- TF32 tensor-core GEMM, cp.async 3-stage ---------------------
// C[M,N] = A[M,K] @ B[K,N]. Inputs already tf32-rounded. 128x128x32 tiles.
#define STAGES 3
#define GPA 36
#define GPB 136
#define STAGE_U32 (128*GPA + 32*GPB)
#define GEMM_SMEM (STAGES * STAGE_U32 * 4)

template<bool BIAS, bool RELU, bool RES, bool CVTOUT>
__global__ void __launch_bounds__(256, 2) gemm_tc(
    const float* __restrict__ A, const float* __restrict__ B,
    const float* __restrict__ bias, const float* __restrict__ res,
    float* __restrict__ C, int M, int N, int K)
{
    extern __shared__ unsigned smg[];
    const int tid  = threadIdx.x;
    const int bm   = blockIdx.y * 128, bn = blockIdx.x * 128;
    const int warp = tid >> 5, lane = tid & 31;
    const int wm   = (warp >> 2) << 6;
    const int wn   = (warp & 3) << 5;
    const int g    = lane >> 2, q = lane & 3;

    const int arow = tid >> 3, acol = (tid & 7) << 2;
    const int brow = tid >> 5, bcol = (tid & 31) << 2;

    const float* Ag = A + (size_t)(bm + arow) * K + acol;
    const float* Bg = B + (size_t)brow * N + bn + bcol;
    const unsigned sbase = (unsigned)__cvta_generic_to_shared(smg);

    float acc[4][4][4];
    #pragma unroll
    for (int mi = 0; mi < 4; mi++)
        #pragma unroll
        for (int nj = 0; nj < 4; nj++)
            #pragma unroll
            for (int e = 0; e < 4; e++) acc[mi][nj][e] = 0.f;

    const int nt = K >> 5;

    #define G_ISSUE(buf, kt) do { \
        unsigned ab_ = sbase + (buf) * (STAGE_U32 * 4); \
        unsigned bb_ = ab_ + 128 * GPA * 4; \
        const float* Ap_ = Ag + (kt) * 32; \
        const float* Bp_ = Bg + (size_t)(kt) * 32 * N; \
        _Pragma("unroll") \
        for (int i_ = 0; i_ < 4; i_++) { \
            cp16(ab_ + ((arow + 32 * i_) * GPA + acol) * 4, Ap_ + (size_t)(32 * i_) * K); \
            cp16(bb_ + ((brow + 8 * i_) * GPB + bcol) * 4, Bp_ + (size_t)(8 * i_) * N); \
        } \
    } while (0)

    #pragma unroll
    for (int s = 0; s < STAGES - 1; s++) {
        if (s < nt) G_ISSUE(s, s);
        CP_COMMIT();
    }

    for (int kt = 0; kt < nt; kt++) {
        CP_WAIT(STAGES - 2);
        __syncthreads();
        int nl = kt + STAGES - 1;
        if (nl < nt) {
            int buf = nl % STAGES;
            G_ISSUE(buf, nl);
        }
        CP_COMMIT();

        const unsigned* Ab = smg + (kt % STAGES) * STAGE_U32;
        const unsigned* Bb = Ab + 128 * GPA;
        #pragma unroll
        for (int ks = 0; ks < 4; ks++) {
            const int kk = ks << 3;
            unsigned af[4][4], bf[4][2];
            #pragma unroll
            for (int mi = 0; mi < 4; mi++) {
                int r = wm + (mi << 4) + g;
                af[mi][0] = Ab[r * GPA + kk + q];
                af[mi][1] = Ab[(r + 8) * GPA + kk + q];
                af[mi][2] = Ab[r * GPA + kk + q + 4];
                af[mi][3] = Ab[(r + 8) * GPA + kk + q + 4];
            }
            #pragma unroll
            for (int nj = 0; nj < 4; nj++) {
                int c = wn + (nj << 3) + g;
                bf[nj][0] = Bb[(kk + q) * GPB + c];
                bf[nj][1] = Bb[(kk + q + 4) * GPB + c];
            }
            #pragma unroll
            for (int mi = 0; mi < 4; mi++)
                #pragma unroll
                for (int nj = 0; nj < 4; nj++)
                    MMA_TF32(acc[mi][nj], af[mi], bf[nj]);
        }
    }

    // epilogue
    #pragma unroll
    for (int mi = 0; mi < 4; mi++) {
        int r = bm + wm + (mi << 4) + g;
        #pragma unroll
        for (int nj = 0; nj < 4; nj++) {
            int c = bn + wn + (nj << 3) + (q << 1);
            float2 v0, v1;
            v0.x = acc[mi][nj][0]; v0.y = acc[mi][nj][1];
            v1.x = acc[mi][nj][2]; v1.y = acc[mi][nj][3];
            if (BIAS) {
                float2 bv = *reinterpret_cast<const float2*>(bias + c);
                v0.x += bv.x; v0.y += bv.y; v1.x += bv.x; v1.y += bv.y;
            }
            if (RELU) {
                v0.x = fmaxf(v0.x, 0.f); v0.y = fmaxf(v0.y, 0.f);
                v1.x = fmaxf(v1.x, 0.f); v1.y = fmaxf(v1.y, 0.f);
            }
            if (RES) {
                float2 r0 = *reinterpret_cast<const float2*>(res + (size_t)r * N + c);
                float2 r1 = *reinterpret_cast<const float2*>(res + (size_t)(r + 8) * N + c);
                v0.x += r0.x; v0.y += r0.y; v1.x += r1.x; v1.y += r1.y;
            }
            if (CVTOUT) {
                v0.x = __uint_as_float(f2tf(v0.x)); v0.y = __uint_as_float(f2tf(v0.y));
                v1.x = __uint_as_float(f2tf(v1.x)); v1.y = __uint_as_float(f2tf(v1.y));
            }
            *reinterpret_cast<float2*>(C + (size_t)r * N + c) = v0;
            *reinterpret_cast<float2*>(C + (size_t)(r + 8) * N + c) = v1;
        }
    }
}

// ---------------- TF32 flash attention ---------------------------------------
// 128 q rows/block, 8 warps x 16 rows. 64-key tiles, double-buffered K/V via
// cp.async. Ps aliases Qs (per-warp rows -> no cross-warp hazard).
#define AQS 68
#define AKS 68
#define AVS 72
#define APS 68
#define ATT_SMEM ((128*AQS + 2*64*AKS + 2*64*AVS) * 4)

__global__ void __launch_bounds__(256, 2) attn_tc(
    const float* __restrict__ qg, const float* __restrict__ kg,
    const float* __restrict__ vg, float* __restrict__ og)
{
    extern __shared__ unsigned sma[];
    unsigned* Qs = sma;
    unsigned* Ks = Qs + 128 * AQS;        // [2][64*AKS]
    unsigned* Vs = Ks + 2 * 64 * AKS;     // [2][64*AVS]
    unsigned* Ps = Qs;                    // alias

    const int tid  = threadIdx.x;
    const int warp = tid >> 5, lane = tid & 31;
    const int g    = lane >> 2, q4 = lane & 3;
    const int bh   = blockIdx.y;
    const int b    = bh >> 4, h = bh & 15;
    const int q0   = blockIdx.x * 128;
    const size_t base = ((size_t)b * SSQ) * DIMX + h * HD;
    const int r0 = warp << 4;
    const unsigned sbase = (unsigned)__cvta_generic_to_shared(sma);
    const unsigned ksb = sbase + 128 * AQS * 4;
    const unsigned vsb = ksb + 2 * 64 * AKS * 4;

    // Q tile via cp.async
    #pragma unroll
    for (int i = 0; i < 8; i++) {
        int f = tid + (i << 8);
        int row = f >> 4;
        int d4 = (f & 15) << 2;
        cp16(sbase + (row * AQS + d4) * 4, qg + base + (size_t)(q0 + row) * DIMX + d4);
    }
    CP_COMMIT();

    #define A_ISSUE(buf, kt) do { \
        _Pragma("unroll") \
        for (int i_ = 0; i_ < 4; i_++) { \
            int f_ = tid + (i_ << 8); \
            int key_ = f_ >> 4; \
            int d4_ = (f_ & 15) << 2; \
            size_t go_ = base + (size_t)((kt) + key_) * DIMX + d4_; \
            cp16(ksb + ((buf) * 64 * AKS + key_ * AKS + d4_) * 4, kg + go_); \
            cp16(vsb + ((buf) * 64 * AVS + key_ * AVS + d4_) * 4, vg + go_); \
        } \
    } while (0)

    // wait for Q, preload fragments
    CP_WAIT(0);
    __syncthreads();
    unsigned aq[8][4];
    #pragma unroll
    for (int ks = 0; ks < 8; ks++) {
        int kk = ks << 3;
        aq[ks][0] = Qs[(r0 + g) * AQS + kk + q4];
        aq[ks][1] = Qs[(r0 + 8 + g) * AQS + kk + q4];
        aq[ks][2] = Qs[(r0 + g) * AQS + kk + q4 + 4];
        aq[ks][3] = Qs[(r0 + 8 + g) * AQS + kk + q4 + 4];
    }

    // first K/V tile
    A_ISSUE(0, 0);
    CP_COMMIT();

    float m0 = -1e30f, m1 = -1e30f, l0 = 0.f, l1 = 0.f;
    float oacc[8][4];
    #pragma unroll
    for (int j = 0; j < 8; j++)
        #pragma unroll
        for (int e = 0; e < 4; e++) oacc[j][e] = 0.f;

    const int NKT = SSQ / 64;
    for (int t = 0; t < NKT; t++) {
        __syncthreads();                 // everyone done with buf (t-1)&1
        if (t + 1 < NKT) A_ISSUE((t + 1) & 1, (t + 1) * 64);
        CP_COMMIT();
        CP_WAIT(1);                      // tile t complete, t+1 in flight
        __syncthreads();

        const unsigned* Kb = Ks + (t & 1) * 64 * AKS;
        const unsigned* Vb = Vs + (t & 1) * 64 * AVS;

        // S = Q K^T
        float s[8][4];
        #pragma unroll
        for (int j = 0; j < 8; j++)
            #pragma unroll
            for (int e = 0; e < 4; e++) s[j][e] = 0.f;
        #pragma unroll
        for (int ks = 0; ks < 8; ks++) {
            int kk = ks << 3;
            #pragma unroll
            for (int j = 0; j < 8; j++) {
                unsigned bfr[2];
                bfr[0] = Kb[((j << 3) + g) * AKS + kk + q4];
                bfr[1] = Kb[((j << 3) + g) * AKS + kk + q4 + 4];
                MMA_TF32(s[j], aq[ks], bfr);
            }
        }

        // online softmax (rows within quads)
        float mt0 = -1e30f, mt1 = -1e30f;
        #pragma unroll
        for (int j = 0; j < 8; j++) {
            s[j][0] *= 0.125f; s[j][1] *= 0.125f; s[j][2] *= 0.125f; s[j][3] *= 0.125f;
            mt0 = fmaxf(mt0, fmaxf(s[j][0], s[j][1]));
            mt1 = fmaxf(mt1, fmaxf(s[j][2], s[j][3]));
        }
        mt0 = fmaxf(mt0, __shfl_xor_sync(0xffffffffu, mt0, 1));
        mt0 = fmaxf(mt0, __shfl_xor_sync(0xffffffffu, mt0, 2));
        mt1 = fmaxf(mt1, __shfl_xor_sync(0xffffffffu, mt1, 1));
        mt1 = fmaxf(mt1, __shfl_xor_sync(0xffffffffu, mt1, 2));
        float mn0 = fmaxf(m0, mt0), mn1 = fmaxf(m1, mt1);
        float corr0 = __expf(m0 - mn0), corr1 = __expf(m1 - mn1);
        m0 = mn0; m1 = mn1;
        float ls0 = 0.f, ls1 = 0.f;
        #pragma unroll
        for (int j = 0; j < 8; j++) {
            float p0 = __expf(s[j][0] - mn0);
            float p1 = __expf(s[j][1] - mn0);
            float p2 = __expf(s[j][2] - mn1);
            float p3 = __expf(s[j][3] - mn1);
            ls0 += p0 + p1; ls1 += p2 + p3;
            uint2 u0; u0.x = f2tf(p0); u0.y = f2tf(p1);
            uint2 u1; u1.x = f2tf(p2); u1.y = f2tf(p3);
            *reinterpret_cast<uint2*>(Ps + (r0 + g) * APS + (j << 3) + (q4 << 1)) = u0;
            *reinterpret_cast<uint2*>(Ps + (r0 + 8 + g) * APS + (j << 3) + (q4 << 1)) = u1;
        }
        ls0 += __shfl_xor_sync(0xffffffffu, ls0, 1);
        ls0 += __shfl_xor_sync(0xffffffffu, ls0, 2);
        ls1 += __shfl_xor_sync(0xffffffffu, ls1, 1);
        ls1 += __shfl_xor_sync(0xffffffffu, ls1, 2);
        l0 = l0 * corr0 + ls0;
        l1 = l1 * corr1 + ls1;
        #pragma unroll
        for (int j = 0; j < 8; j++) {
            oacc[j][0] *= corr0; oacc[j][1] *= corr0;
            oacc[j][2] *= corr1; oacc[j][3] *= corr1;
        }
        __syncwarp();

        // O += P @ V
        #pragma unroll
        for (int ks = 0; ks < 8; ks++) {
            int kk = ks << 3;
            unsigned ap[4];
            ap[0] = Ps[(r0 + g) * APS + kk + q4];
            ap[1] = Ps[(r0 + 8 + g) * APS + kk + q4];
            ap[2] = Ps[(r0 + g) * APS + kk + q4 + 4];
            ap[3] = Ps[(r0 + 8 + g) * APS + kk + q4 + 4];
            #pragma unroll
            for (int j = 0; j < 8; j++) {
                unsigned bfr[2];
                bfr[0] = Vb[(kk + q4) * AVS + (j << 3) + g];
                bfr[1] = Vb[(kk + q4 + 4) * AVS + (j << 3) + g];
                MMA_TF32(oacc[j], ap, bfr);
            }
        }
    }

    // epilogue (tf32-rounded: feeds Wo GEMM)
    float il0 = 1.0f / l0, il1 = 1.0f / l1;
    #pragma unroll
    for (int j = 0; j < 8; j++) {
        uint2 v0, v1;
        v0.x = f2tf(oacc[j][0] * il0); v0.y = f2tf(oacc[j][1] * il0);
        v1.x = f2tf(oacc[j][2] * il1); v1.y = f2tf(oacc[j][3] * il1);
        size_t o0 = base + (size_t)(q0 + r0 + g) * DIMX + (j << 3) + (q4 << 1);
        size_t o1 = base + (size_t)(q0 + r0 + 8 + g) * DIMX + (j << 3) + (q4 << 1);
        *reinterpret_cast<uint2*>(og + o0) = v0;
        *reinterpret_cast<uint2*>(og + o1) = v1;
    }
}

// ---------------- launch ------------------------------------------------------
extern "C" void kernel_launch(void* const* d_in, const int* in_sizes, int n_in,
                              void* d_out, int out_size)
{
    const float* x    = (const float*)d_in[0];
    const float* wq   = (const float*)d_in[2];
    const float* wk   = (const float*)d_in[3];
    const float* wv   = (const float*)d_in[4];
    const float* wo   = (const float*)d_in[5];
    const float* w_up = (const float*)d_in[6];
    const float* b_up = (const float*)d_in[7];
    const float* w_dn = (const float*)d_in[8];
    const float* b_dn = (const float*)d_in[9];
    const float* l1a  = (const float*)d_in[10];
    const float* l1b  = (const float*)d_in[11];
    const float* l2a  = (const float*)d_in[12];
    const float* l2b  = (const float*)d_in[13];
    float* out = (float*)d_out;

    float *h, *qb, *kb, *vb, *attn, *x2, *ffh, *wc;
    cudaGetSymbolAddress((void**)&h,    g_h);
    cudaGetSymbolAddress((void**)&qb,   g_q);
    cudaGetSymbolAddress((void**)&kb,   g_k);
    cudaGetSymbolAddress((void**)&vb,   g_v);
    cudaGetSymbolAddress((void**)&attn, g_attn);
    cudaGetSymbolAddress((void**)&x2,   g_x2);
    cudaGetSymbolAddress((void**)&ffh,  g_ffh);
    cudaGetSymbolAddress((void**)&wc,   g_wc);

    float* wq_c = wc;
    float* wk_c = wc + 1 * DIMX * DIMX;
    float* wv_c = wc + 2 * DIMX * DIMX;
    float* wo_c = wc + 3 * DIMX * DIMX;
    float* wu_c = wc + 4 * DIMX * DIMX;
    float* wd_c = wu_c + DIMX * DFF;

    cudaFuncSetAttribute(gemm_tc<false,false,false,true >, cudaFuncAttributeMaxDynamicSharedMemorySize, GEMM_SMEM);
    cudaFuncSetAttribute(gemm_tc<false,false,true ,false>, cudaFuncAttributeMaxDynamicSharedMemorySize, GEMM_SMEM);
    cudaFuncSetAttribute(gemm_tc<true ,true ,false,true >, cudaFuncAttributeMaxDynamicSharedMemorySize, GEMM_SMEM);
    cudaFuncSetAttribute(gemm_tc<true ,false,true ,false>, cudaFuncAttributeMaxDynamicSharedMemorySize, GEMM_SMEM);
    cudaFuncSetAttribute(attn_tc, cudaFuncAttributeMaxDynamicSharedMemorySize, ATT_SMEM);

    dim3 thr(256);

    // weight pre-round to tf32
    int nw1 = DIMX * DIMX / 4, nw2 = DIMX * DFF / 4;
    cvt_kernel<<<(nw1 + 255) / 256, thr>>>(wq,   wq_c, nw1);
    cvt_kernel<<<(nw1 + 255) / 256, thr>>>(wk,   wk_c, nw1);
    cvt_kernel<<<(nw1 + 255) / 256, thr>>>(wv,   wv_c, nw1);
    cvt_kernel<<<(nw1 + 255) / 256, thr>>>(wo,   wo_c, nw1);
    cvt_kernel<<<(nw2 + 255) / 256, thr>>>(w_up, wu_c, nw2);
    cvt_kernel<<<(nw2 + 255) / 256, thr>>>(w_dn, wd_c, nw2);

    // h = LN1(x)  (tf32-rounded)
    ln_kernel<<<MTOT, thr>>>(x, l1a, l1b, h);

    // q, k, v projections (outputs tf32-rounded for attention)
    gemm_tc<false,false,false,true><<<dim3(DIMX/128, MTOT/128), thr, GEMM_SMEM>>>(h, wq_c, nullptr, nullptr, qb, MTOT, DIMX, DIMX);
    gemm_tc<false,false,false,true><<<dim3(DIMX/128, MTOT/128), thr, GEMM_SMEM>>>(h, wk_c, nullptr, nullptr, kb, MTOT, DIMX, DIMX);
    gemm_tc<false,false,false,true><<<dim3(DIMX/128, MTOT/128), thr, GEMM_SMEM>>>(h, wv_c, nullptr, nullptr, vb, MTOT, DIMX, DIMX);

    // attention (output tf32-rounded)
    attn_tc<<<dim3(SSQ/128, BB*NH), thr, ATT_SMEM>>>(qb, kb, vb, attn);

    // x2 = x + attn @ wo  (full fp32 out)
    gemm_tc<false,false,true,false><<<dim3(DIMX/128, MTOT/128), thr, GEMM_SMEM>>>(attn, wo_c, nullptr, x, x2, MTOT, DIMX, DIMX);

    // h = LN2(x2)
    ln_kernel<<<MTOT, thr>>>(x2, l2a, l2b, h);

    // ffh = relu(h @ w_up + b_up)  (tf32-rounded)
    gemm_tc<true,true,false,true><<<dim3(DFF/128, MTOT/128), thr, GEMM_SMEM>>>(h, wu_c, b_up, nullptr, ffh, MTOT, DFF, DIMX);

    // out = x2 + ffh @ w_down + b_down  (full fp32)
    gemm_tc<true,false,true,false><<<dim3(DIMX/128, MTOT/128), thr, GEMM_SMEM>>>(ffh, wd_c, b_dn, x2, out, MTOT, DIMX, DFF);
}